// round 9
// baseline (speedup 1.0000x reference)
#include <cuda_runtime.h>
#include <cstdint>

// Problem constants
#define T_LEN 2048
#define BATCH 32
#define HID   256
#define G3    768    // 3H (weight leading dim)
#define N2    512    // only first 2H pre-columns matter (c_pre is dead)
#define NSCAN 128    // scan blocks: each owns 2 h-cols of BOTH layers
#define NTOT  148
#define NWORK (NTOT - NSCAN)   // 20 gemm workers
#define NTILE 8192   // 1024 t-pair rows * 8 col tiles

// ---------------------------------------------------------------------------
// Device scratch
// ---------------------------------------------------------------------------
__device__ float g_X[(size_t)T_LEN * N2 * BATCH];  // x@Wih0+b0, [t][c(512)][b(32)]
__device__ float g_h0[2][HID * BATCH];             // h0(t) in slot t&1, layout [k][r]
__device__ float g_h1[2][HID * BATCH];             // h1(t) in slot t&1
__device__ unsigned g_flag[NSCAN * 8];             // monotonic progress flags
__device__ unsigned g_tcnt[T_LEN / 2];             // gemm tile counters (8/run/row)
__device__ unsigned g_run;                         // completed-run epoch

// ---------------------------------------------------------------------------
// Packed f32x2 helpers
// ---------------------------------------------------------------------------
__device__ __forceinline__ unsigned long long pack2(float v) {
    unsigned long long r;
    asm("mov.b64 %0, {%1, %1};" : "=l"(r) : "f"(v));
    return r;
}
__device__ __forceinline__ void fma2(unsigned long long& d,
                                     unsigned long long a, unsigned long long b) {
    asm("fma.rn.f32x2 %0, %1, %2, %0;" : "+l"(d) : "l"(a), "l"(b));
}
__device__ __forceinline__ unsigned long long add2(unsigned long long a,
                                                   unsigned long long b) {
    unsigned long long r;
    asm("add.rn.f32x2 %0, %1, %2;" : "=l"(r) : "l"(a), "l"(b));
    return r;
}
__device__ __forceinline__ void unpack2(unsigned long long v, float& lo, float& hi) {
    asm("mov.b64 {%0, %1}, %2;" : "=f"(lo), "=f"(hi) : "l"(v));
}

// ---------------------------------------------------------------------------
// GEMM worker: grid-strided 64x64x256 tiles of g_X = input @ Wih0[:,:512]+b0.
// ---------------------------------------------------------------------------
__device__ void gemm_worker(int wb, const float* __restrict__ A,
                            const float* __restrict__ W,
                            const float* __restrict__ bias,
                            float* smem, int Lmax)
{
    float (*As)[65] = (float(*)[65])smem;
    float (*Bs)[64] = (float(*)[64])(smem + 32 * 65);

    const int tid = threadIdx.x;
    const int tx  = tid & 15;
    const int ty  = tid >> 4;
    const int ar  = tid >> 2;
    const int ak  = (tid & 3) * 8;
    const int bk  = tid >> 3;
    const int bc  = (tid & 7) * 8;

    for (int n = wb; n < NTILE; n += NWORK) {
        const int bx = n >> 3;
        if (2 * bx >= Lmax) break;
        const int m0 = bx * 64;
        const int n0 = (n & 7) * 64;

        unsigned long long acc2[4][2];
#pragma unroll
        for (int i = 0; i < 4; i++) { acc2[i][0] = 0ull; acc2[i][1] = 0ull; }

        for (int k0 = 0; k0 < 256; k0 += 32) {
            float4 a0  = *(const float4*)&A[(size_t)(m0 + ar) * 256 + k0 + ak];
            float4 a1  = *(const float4*)&A[(size_t)(m0 + ar) * 256 + k0 + ak + 4];
            float4 b0v = *(const float4*)&W[(size_t)(k0 + bk) * G3 + n0 + bc];
            float4 b1v = *(const float4*)&W[(size_t)(k0 + bk) * G3 + n0 + bc + 4];

            As[ak + 0][ar] = a0.x; As[ak + 1][ar] = a0.y;
            As[ak + 2][ar] = a0.z; As[ak + 3][ar] = a0.w;
            As[ak + 4][ar] = a1.x; As[ak + 5][ar] = a1.y;
            As[ak + 6][ar] = a1.z; As[ak + 7][ar] = a1.w;
            *(float4*)&Bs[bk][bc]     = b0v;
            *(float4*)&Bs[bk][bc + 4] = b1v;
            __syncthreads();

#pragma unroll
            for (int kk = 0; kk < 32; kk++) {
                const ulonglong2 bq = *(const ulonglong2*)&Bs[kk][ty * 4];
#pragma unroll
                for (int ri = 0; ri < 4; ri++) {
                    const unsigned long long av = pack2(As[kk][tx * 4 + ri]);
                    fma2(acc2[ri][0], bq.x, av);
                    fma2(acc2[ri][1], bq.y, av);
                }
            }
            __syncthreads();
        }

        float accf[4][4];
#pragma unroll
        for (int ri = 0; ri < 4; ri++) {
            unpack2(acc2[ri][0], accf[ri][0], accf[ri][1]);
            unpack2(acc2[ri][1], accf[ri][2], accf[ri][3]);
        }

        const int t  = bx * 2 + (tx >> 3);
        const int bb = (tx & 7) * 4;
#pragma unroll
        for (int ci = 0; ci < 4; ci++) {
            const int c = n0 + ty * 4 + ci;
            const float bv = bias[c];
            float4 v = make_float4(accf[0][ci] + bv, accf[1][ci] + bv,
                                   accf[2][ci] + bv, accf[3][ci] + bv);
            *(float4*)&g_X[((size_t)t * N2 + c) * BATCH + bb] = v;
        }

        __threadfence();
        __syncthreads();
        if (tid == 0) {
            asm volatile("red.release.gpu.global.add.u32 [%0], %1;"
                         :: "l"(&g_tcnt[bx]), "r"(1u) : "memory");
        }
    }
}

// ---------------------------------------------------------------------------
// ONE kernel, 148 blocks (1/SM):
//   blocks 0..127 : scan; block b owns h-cols {2b,2b+1} of BOTH layers.
//     warps 0-3: layer-0 dot (K=256), warps 4-7: layer-1 dot (K=512).
//   blocks 128..147: gemm workers.
// Round i: layer-0 computes h0(i) (i<Lmax); layer-1 computes h1(i-1) (i>=1).
// Staged hs = [h1(i-2) (k 0..255) ; h0(i-1) (k 256..511)], [k][r] swizzled
// with chunk ^= (k>>3)&7 (conflict-free for both layers' k-slicings).
// ---------------------------------------------------------------------------
__global__ __launch_bounds__(256, 1) void fused_all(
    const float* __restrict__ input,
    const float* __restrict__ Whh0,
    const float* __restrict__ Whh1,
    const float* __restrict__ Wih0,
    const float* __restrict__ Wih1,
    const float* __restrict__ b0,
    const float* __restrict__ b1,
    const int*   __restrict__ length,
    float* __restrict__ out1,
    float* __restrict__ hn)
{
    extern __shared__ float smem[];
    const int bid = blockIdx.x;
    const int tid = threadIdx.x;

    int Lmax = 0;
#pragma unroll 8
    for (int r = 0; r < BATCH; r++) Lmax = max(Lmax, length[r]);

    if (bid >= NSCAN) {
        gemm_worker(bid - NSCAN, input, Wih0, b0, smem, Lmax);
        return;
    }

    float* hs    = smem;                  // [512][32] swizzled (64KB)
    float* red   = smem + N2 * BATCH;     // [2 grp][4 w][4 ci][34]
    float* out_s = red + 2 * 4 * 4 * 34;  // [32][2]
    float4* hs4  = (float4*)hs;
    const ulonglong2* hsU = (const ulonglong2*)hs;

    const int wid  = tid >> 5;
    const int lane = tid & 31;
    const int grp  = wid >> 2;          // 0 = layer-0 warps, 1 = layer-1 warps
    const int ww   = wid & 3;           // warp within group
    const int kslice = lane & 7;
    const int rgrp   = lane >> 3;       // 4 row groups x 8 rows
    const int c0   = 2 * bid;           // first owned h-col

    const int kbase = grp ? (ww * 128 + kslice * 8)
                          : (256 + ww * 64 + kslice * 8);
    const int swz = (kbase >> 3) & 7;   // constant per thread
    const int o0  = (rgrp * 2)     ^ swz;
    const int o1  = (rgrp * 2 + 1) ^ swz;

    const unsigned R     = *(volatile unsigned*)&g_run;
    const unsigned fbase = R * (unsigned)(Lmax + 1);
    const unsigned tbase = R * 8u;

    // ---- weights in registers: 4 precols x (8 | 16) k ----
    float w[4][16];
    if (grp == 0) {
#pragma unroll
        for (int kk = 0; kk < 8; kk++) {
            const int krow = kbase - 256 + kk;   // row of Whh0
#pragma unroll
            for (int ci = 0; ci < 4; ci++) {
                const int pc = (ci < 2) ? (c0 + ci) : (HID + c0 + ci - 2);
                w[ci][kk] = Whh0[(size_t)krow * G3 + pc];
            }
        }
#pragma unroll
        for (int kk = 8; kk < 16; kk++)
#pragma unroll
            for (int ci = 0; ci < 4; ci++) w[ci][kk] = 0.f;
    } else {
#pragma unroll
        for (int kk = 0; kk < 16; kk++) {
            const int kst = kbase + (kk & 7) + ((kk >> 3) << 6);  // staged k
            const float* W = (kst < 256) ? Whh1 : Wih1;
            const int krow = kst & 255;
#pragma unroll
            for (int ci = 0; ci < 4; ci++) {
                const int pc = (ci < 2) ? (c0 + ci) : (HID + c0 + ci - 2);
                w[ci][kk] = W[(size_t)krow * G3 + pc];
            }
        }
    }

    // gate-thread setup: layer gl uses threads [gl*128, gl*128+64)
    const int gl   = tid >> 7;
    const bool gate_th = ((tid & 127) < 64);
    const int gr   = tid & 31;
    const int gc   = (tid >> 5) & 1;
    const int gj   = c0 + gc;
    const int glen = length[gr];
    float gbh = 0.f, gbt = 0.f;
    if (gl == 1 && gate_th) {
        gbh = b1[gj];
        gbt = b1[HID + gj];
    }

    for (int idx = tid; idx < BATCH * 2; idx += 256) out_s[idx] = 0.f;

    float hlast = 0.f;
    int rdy_row = 0;

    for (int i = 0; i <= Lmax; i++) {
        const bool act0 = (i < Lmax);
        const bool act1 = (i >= 1);

        // ---- wait: all 128 flags >= i; gemm row (i>>1) ready ----
        if (i > 0 && tid < NSCAN) {
            const unsigned target = fbase + (unsigned)i;
            unsigned v;
            do {
                asm volatile("ld.acquire.gpu.global.u32 %0, [%1];"
                             : "=r"(v) : "l"(&g_flag[tid * 8]) : "memory");
            } while ((int)(v - target) < 0);
        }
        if (tid == 255 && act0 && (i >> 1) >= rdy_row) {
            const unsigned target = tbase + 8u;
            unsigned v;
            do {
                asm volatile("ld.acquire.gpu.global.u32 %0, [%1];"
                             : "=r"(v) : "l"(&g_tcnt[i >> 1]) : "memory");
            } while ((int)(v - target) < 0);
            rdy_row = (i >> 1) + 1;
        }
        __syncthreads();

        // ---- prefetch layer-0 x-term ----
        float xh = 0.f, xt = 0.f;
        if (gl == 0 && gate_th && act0) {
            const size_t bo = ((size_t)i * N2 + gj) * BATCH + gr;
            xh = __ldg(&g_X[bo]);
            xt = __ldg(&g_X[bo + (size_t)HID * BATCH]);
        }

        // ---- stage [h1(i-2) ; h0(i-1)] ----
        if (i >= 2) {
            const float4* s = (const float4*)g_h1[i & 1];
            for (int idx = tid; idx < 2048; idx += 256) {
                const int k = idx >> 3, c = idx & 7;
                hs4[k * 8 + (c ^ ((k >> 3) & 7))] = __ldcg(s + idx);
            }
        } else {
            const float4 z = make_float4(0.f, 0.f, 0.f, 0.f);
            for (int idx = tid; idx < 2048; idx += 256) hs4[idx] = z;
        }
        if (i >= 1) {
            const float4* s = (const float4*)g_h0[(i + 1) & 1];
            for (int idx = tid; idx < 2048; idx += 256) {
                const int k = 256 + (idx >> 3), c = idx & 7;
                hs4[k * 8 + (c ^ ((k >> 3) & 7))] = __ldcg(s + idx);
            }
        } else {
            const float4 z = make_float4(0.f, 0.f, 0.f, 0.f);
            for (int idx = tid; idx < 2048; idx += 256) {
                const int k = 256 + (idx >> 3), c = idx & 7;
                hs4[k * 8 + (c ^ ((k >> 3) & 7))] = z;
            }
        }
        __syncthreads();

        // ---- dot ----
        const bool myact = grp ? act1 : act0;
        if (myact) {
            unsigned long long acc[4][4];
#pragma unroll
            for (int ci = 0; ci < 4; ci++)
#pragma unroll
                for (int p = 0; p < 4; p++) acc[ci][p] = 0ull;

            if (grp == 0) {
#pragma unroll
                for (int kk = 0; kk < 8; kk++) {
                    const int b4 = (kbase + kk) * 8;
                    const ulonglong2 ha = *(const ulonglong2*)&hs4[b4 + o0];
                    const ulonglong2 hb = *(const ulonglong2*)&hs4[b4 + o1];
#pragma unroll
                    for (int ci = 0; ci < 4; ci++) {
                        const unsigned long long w2 = pack2(w[ci][kk]);
                        fma2(acc[ci][0], ha.x, w2);
                        fma2(acc[ci][1], ha.y, w2);
                        fma2(acc[ci][2], hb.x, w2);
                        fma2(acc[ci][3], hb.y, w2);
                    }
                }
            } else {
#pragma unroll
                for (int kk = 0; kk < 16; kk++) {
                    const int kst = kbase + (kk & 7) + ((kk >> 3) << 6);
                    const int b4 = kst * 8;
                    const ulonglong2 ha = *(const ulonglong2*)&hs4[b4 + o0];
                    const ulonglong2 hb = *(const ulonglong2*)&hs4[b4 + o1];
#pragma unroll
                    for (int ci = 0; ci < 4; ci++) {
                        const unsigned long long w2 = pack2(w[ci][kk]);
                        fma2(acc[ci][0], ha.x, w2);
                        fma2(acc[ci][1], ha.y, w2);
                        fma2(acc[ci][2], hb.x, w2);
                        fma2(acc[ci][3], hb.y, w2);
                    }
                }
            }

            // reduce over kslice (lane bits 0..2)
#pragma unroll
            for (int ci = 0; ci < 4; ci++)
#pragma unroll
                for (int p = 0; p < 4; p++) {
                    unsigned long long v = acc[ci][p];
                    v = add2(v, __shfl_xor_sync(0xffffffffu, v, 1));
                    v = add2(v, __shfl_xor_sync(0xffffffffu, v, 2));
                    v = add2(v, __shfl_xor_sync(0xffffffffu, v, 4));
                    acc[ci][p] = v;
                }
            if (kslice == 0) {
#pragma unroll
                for (int ci = 0; ci < 4; ci++)
#pragma unroll
                    for (int p = 0; p < 4; p++)
                        *(unsigned long long*)&red[((grp * 4 + ww) * 4 + ci) * 34
                                                   + rgrp * 8 + 2 * p] = acc[ci][p];
            }
        }
        __syncthreads();

        // ---- gates ----
        const bool gact = gl ? act1 : act0;
        if (gate_th && gact) {
            float sh = 0.f, st = 0.f;
#pragma unroll
            for (int wp = 0; wp < 4; wp++) {
                sh += red[((gl * 4 + wp) * 4 + gc)     * 34 + gr];
                st += red[((gl * 4 + wp) * 4 + gc + 2) * 34 + gr];
            }
            const int t = gl ? (i - 1) : i;
            const float ph = sh + (gl ? gbh : xh);
            const float pt = st + (gl ? gbt : xt);
            const int kst = gl ? gj : (256 + gj);
            const float hprev = hs[kst * 32 +
                (((gr >> 2) ^ ((kst >> 3) & 7)) << 2) + (gr & 3)];
            const float tg    = 1.f / (1.f + __expf(-pt));
            const float cgate = 1.f / (1.f + __expf(-tg));   // bug-faithful
            const float sv    = tanhf(ph) * tg + hprev * cgate;
            const float hnew  = (t < glen) ? sv : hprev;
            hlast = hnew;
            if (gl) {
                g_h1[(i - 1) & 1][gj * BATCH + gr] = hnew;
                out_s[gr * 2 + gc] = hnew;
            } else {
                g_h0[i & 1][gj * BATCH + gr] = hnew;
            }
        }
        __syncthreads();

        // ---- publish ----
        if (tid == 0) {
            asm volatile("st.release.gpu.global.u32 [%0], %1;"
                         :: "l"(&g_flag[bid * 8]), "r"(fbase + (unsigned)(i + 1))
                         : "memory");
        }

        // ---- out1 write off the critical path ----
        if (act1 && tid >= 128 && tid < 160) {
            const int r = tid - 128;
            const float2 v = *(const float2*)&out_s[r * 2];
            *(float2*)&out1[((size_t)(i - 1) * BATCH + r) * HID + c0] = v;
        }
    }

    // ---- epilogue: hn + frozen-tail fill ----
    if (gate_th) {
        if (gl) hn[BATCH * HID + gr * HID + gj] = hlast;
        else    hn[gr * HID + gj] = hlast;
    }
    __syncthreads();
    {
        const int ntail = (T_LEN - Lmax) * BATCH;
        for (int idx = tid; idx < ntail; idx += 256) {
            const int tt = Lmax + (idx >> 5), r = idx & 31;
            *(float2*)&out1[((size_t)tt * BATCH + r) * HID + c0] =
                *(const float2*)&out_s[r * 2];
        }
    }

    // ---- run-completion: block 0 advances the epoch ----
    if (bid == 0) {
        if (tid < NSCAN) {
            const unsigned target = fbase + (unsigned)(Lmax + 1);
            unsigned v;
            do {
                asm volatile("ld.acquire.gpu.global.u32 %0, [%1];"
                             : "=r"(v) : "l"(&g_flag[tid * 8]) : "memory");
            } while ((int)(v - target) < 0);
        }
        __syncthreads();
        if (tid == 0) *(volatile unsigned*)&g_run = R + 1u;
    }
}

// ---------------------------------------------------------------------------
extern "C" void kernel_launch(void* const* d_in, const int* in_sizes, int n_in,
                              void* d_out, int out_size) {
    const float* input  = (const float*)d_in[0];
    const int*   length = (const int*)d_in[1];
    const float* Wih0   = (const float*)d_in[2];
    const float* Whh0   = (const float*)d_in[3];
    const float* b0     = (const float*)d_in[4];
    const float* Wih1   = (const float*)d_in[5];
    const float* Whh1   = (const float*)d_in[6];
    const float* b1     = (const float*)d_in[7];

    float* out1 = (float*)d_out;
    float* hn   = (float*)d_out + (size_t)T_LEN * BATCH * HID;

    const int smem_bytes = (N2 * BATCH + 2 * 4 * 4 * 34 + BATCH * 2) * 4;
    static bool attr_set = false;
    if (!attr_set) {
        cudaFuncSetAttribute(fused_all, cudaFuncAttributeMaxDynamicSharedMemorySize,
                             smem_bytes);
        attr_set = true;
    }

    fused_all<<<NTOT, 256, smem_bytes>>>(
        input, Whh0, Whh1, Wih0, Wih1, b0, b1, length, out1, hn);
}

// round 10
// speedup vs baseline: 1.6812x; 1.6812x over previous
#include <cuda_runtime.h>
#include <cstdint>

// Problem constants
#define T_LEN 2048
#define BATCH 32
#define HID   256
#define G3    768
#define NSCAN 128          // 8 domains x 16 blocks
#define NDOM  8
#define BPD   16           // blocks per domain
#define RPD   4            // batch rows per domain
#define NTOT  148
#define NWORK (NTOT - NSCAN)   // 20 gemm workers
#define NTILE 8192             // 1024 bx (2-row groups) x 8 col tiles

typedef unsigned long long ull;

// ---------------------------------------------------------------------------
// Device scratch
// ---------------------------------------------------------------------------
__device__ float g_X[(size_t)T_LEN * BATCH * 512];   // [m = t*32+b][c 512] row-major
__device__ float g_h0[2][NDOM][HID * RPD];           // [slot][d][k*4 + r]
__device__ float g_h1[2][NDOM][HID * RPD];
__device__ unsigned g_flag[NSCAN * 8];               // monotonic flags (32B apart)
__device__ unsigned g_tcnt[T_LEN / 2];               // gemm counters (8/run per bx)
__device__ unsigned g_run;                           // epoch

// ---------------------------------------------------------------------------
// Packed f32x2 helpers
// ---------------------------------------------------------------------------
__device__ __forceinline__ ull pack2(float v) {
    ull r; asm("mov.b64 %0, {%1, %1};" : "=l"(r) : "f"(v)); return r;
}
__device__ __forceinline__ void fma2(ull& d, ull a, ull b) {
    asm("fma.rn.f32x2 %0, %1, %2, %0;" : "+l"(d) : "l"(a), "l"(b));
}
__device__ __forceinline__ void unpack2(ull v, float& lo, float& hi) {
    asm("mov.b64 {%0, %1}, %2;" : "=f"(lo), "=f"(hi) : "l"(v));
}

// ---------------------------------------------------------------------------
// GEMM worker: grid-strided 64x64x256 tiles; g_X[m][c] = input@Wih0[:,:512]+b0
// ---------------------------------------------------------------------------
__device__ void gemm_worker(int wb, const float* __restrict__ A,
                            const float* __restrict__ W,
                            const float* __restrict__ bias,
                            float* smem, int Lmax)
{
    float (*As)[65] = (float(*)[65])smem;
    float (*Bs)[64] = (float(*)[64])(smem + 32 * 65);

    const int tid = threadIdx.x;
    const int tx  = tid & 15;
    const int ty  = tid >> 4;
    const int ar  = tid >> 2;
    const int ak  = (tid & 3) * 8;
    const int bk  = tid >> 3;
    const int bc  = (tid & 7) * 8;

    for (int n = wb; n < NTILE; n += NWORK) {
        const int bx = n >> 3;
        if (2 * bx >= Lmax) break;
        const int m0 = bx * 64;
        const int n0 = (n & 7) * 64;

        ull acc2[4][2];
#pragma unroll
        for (int i = 0; i < 4; i++) { acc2[i][0] = 0ull; acc2[i][1] = 0ull; }

        for (int k0 = 0; k0 < 256; k0 += 32) {
            float4 a0  = *(const float4*)&A[(size_t)(m0 + ar) * 256 + k0 + ak];
            float4 a1  = *(const float4*)&A[(size_t)(m0 + ar) * 256 + k0 + ak + 4];
            float4 b0v = *(const float4*)&W[(size_t)(k0 + bk) * G3 + n0 + bc];
            float4 b1v = *(const float4*)&W[(size_t)(k0 + bk) * G3 + n0 + bc + 4];

            As[ak + 0][ar] = a0.x; As[ak + 1][ar] = a0.y;
            As[ak + 2][ar] = a0.z; As[ak + 3][ar] = a0.w;
            As[ak + 4][ar] = a1.x; As[ak + 5][ar] = a1.y;
            As[ak + 6][ar] = a1.z; As[ak + 7][ar] = a1.w;
            *(float4*)&Bs[bk][bc]     = b0v;
            *(float4*)&Bs[bk][bc + 4] = b1v;
            __syncthreads();

#pragma unroll
            for (int kk = 0; kk < 32; kk++) {
                const ulonglong2 bq = *(const ulonglong2*)&Bs[kk][ty * 4];
#pragma unroll
                for (int ri = 0; ri < 4; ri++) {
                    const ull av = pack2(As[kk][tx * 4 + ri]);
                    fma2(acc2[ri][0], bq.x, av);
                    fma2(acc2[ri][1], bq.y, av);
                }
            }
            __syncthreads();
        }

        const float4 bv = *(const float4*)&bias[n0 + ty * 4];
#pragma unroll
        for (int ri = 0; ri < 4; ri++) {
            float4 v;
            unpack2(acc2[ri][0], v.x, v.y);
            unpack2(acc2[ri][1], v.z, v.w);
            v.x += bv.x; v.y += bv.y; v.z += bv.z; v.w += bv.w;
            *(float4*)&g_X[(size_t)(m0 + tx * 4 + ri) * 512 + n0 + ty * 4] = v;
        }

        __threadfence();
        __syncthreads();
        if (tid == 0) {
            asm volatile("red.release.gpu.global.add.u32 [%0], %1;"
                         :: "l"(&g_tcnt[bx]), "r"(1u) : "memory");
        }
    }
}

// ---------------------------------------------------------------------------
// ONE kernel, 148 blocks (1/SM):
//   blocks 0..127: scan, 8 independent domains x 16 blocks; domain d owns
//     batch rows [4d,4d+4); block owns 16 h-cols (c0..c0+15) of BOTH layers.
//   blocks 128..147: gemm workers.
// Round i (per domain): L0 computes h0(i) if i<Ld; L1 computes h1(i-1) if i>=1.
// Staged hs4 = [h1(i-2) k0..255 ; h0(i-1) k256..511], one float4 (4 rows) per k.
// Dot: lane = precol (32 precols/layer/block), warp = k-quarter. No shuffles.
// hprev lives in the gate thread's register across all rounds.
// ---------------------------------------------------------------------------
__global__ __launch_bounds__(256, 1) void fused_all(
    const float* __restrict__ input,
    const float* __restrict__ Whh0,
    const float* __restrict__ Whh1,
    const float* __restrict__ Wih0,
    const float* __restrict__ Wih1,
    const float* __restrict__ b0,
    const float* __restrict__ b1,
    const int*   __restrict__ length,
    float* __restrict__ out1,
    float* __restrict__ hn)
{
    extern __shared__ float smem[];
    const int bid = blockIdx.x;
    const int tid = threadIdx.x;

    int Lmax = 0;
#pragma unroll 8
    for (int r = 0; r < BATCH; r++) Lmax = max(Lmax, length[r]);

    if (bid >= NSCAN) {
        gemm_worker(bid - NSCAN, input, Wih0, b0, smem, Lmax);
        return;
    }

    // ---- scan layout ----
    float4* hs4  = (float4*)smem;          // [512] float4 (k-major, 4 rows) 8KB
    float*  red  = smem + 512 * 4;         // [2l][4q][32p][4r] 4KB
    float*  outs = red + 2 * 4 * 32 * 4;   // [4r][16j] 256B

    const int d   = bid >> 4;
    const int blk = bid & 15;
    const int c0  = blk * 16;

    int Ld = 0;
#pragma unroll
    for (int r = 0; r < RPD; r++) Ld = max(Ld, length[4 * d + r]);

    const unsigned R     = *(volatile unsigned*)&g_run;
    const unsigned fbase = R * (unsigned)(Ld + 2);
    const unsigned tbase = R * 8u;

    // ---- dot decomposition: warp = (layer, k-quarter), lane = precol ----
    const int wid  = tid >> 5;
    const int lane = tid & 31;
    const int l_w  = wid >> 2;          // 0: layer-0 warps, 1: layer-1 warps
    const int q    = wid & 3;           // k-quarter
    const int pc   = (lane < 16) ? (c0 + lane) : (256 + c0 + lane - 16);

    // weights: L0 thread 64, L1 thread 128 (register-resident)
    float w[128];
    if (l_w == 0) {
#pragma unroll
        for (int kk = 0; kk < 64; kk++)
            w[kk] = Whh0[(size_t)(q * 64 + kk) * G3 + pc];
    } else {
#pragma unroll
        for (int kk = 0; kk < 128; kk++) {
            const int k = q * 128 + kk;
            w[kk] = (k < 256) ? Whh1[(size_t)k * G3 + pc]
                              : Wih1[(size_t)(k - 256) * G3 + pc];
        }
    }

    // ---- gate threads: tid<128; (gl, j, r); hprev in register ----
    const int  gl  = tid >> 6;          // meaningful for tid<128
    const int  g   = tid & 63;
    const int  gj  = g >> 2;
    const int  gr  = g & 3;
    const bool is_gate = (tid < 128);
    const int  glen = length[4 * d + gr];
    float gbh = 0.f, gbt = 0.f;
    if (is_gate && gl == 1) {
        gbh = b1[c0 + gj];
        gbt = b1[256 + c0 + gj];
    }
    float hcur = 0.f;
    int rdy = 0;

    for (int i = 0; i <= Ld; i++) {
        const bool act0 = (i < Ld);
        const bool act1 = (i >= 1);

        // ---- wait: 16 domain flags >= i; gemm row pair ready ----
        if (i > 0 && tid < BPD) {
            const unsigned target = fbase + (unsigned)i;
            unsigned v;
            do {
                asm volatile("ld.acquire.gpu.global.u32 %0, [%1];"
                             : "=r"(v) : "l"(&g_flag[(d * BPD + tid) * 8]) : "memory");
            } while ((int)(v - target) < 0);
        }
        if (tid == 255 && act0 && (i >> 1) >= rdy) {
            const unsigned target = tbase + 8u;
            unsigned v;
            do {
                asm volatile("ld.acquire.gpu.global.u32 %0, [%1];"
                             : "=r"(v) : "l"(&g_tcnt[i >> 1]) : "memory");
            } while ((int)(v - target) < 0);
            rdy = (i >> 1) + 1;
        }
        __syncthreads();   // A

        // ---- prefetch L0 x-term (consumed ~1500 cyc later at gates) ----
        float xh = 0.f, xt = 0.f;
        if (is_gate && gl == 0 && act0) {
            const size_t m = (size_t)i * BATCH + 4 * d + gr;
            xh = __ldg(&g_X[m * 512 + c0 + gj]);
            xt = __ldg(&g_X[m * 512 + 256 + c0 + gj]);
        }

        // ---- stage h (2 coalesced float4 loads per thread) ----
        {
            float4 v = make_float4(0.f, 0.f, 0.f, 0.f);
            if (i >= 2) v = __ldcg((const float4*)g_h1[i & 1][d] + tid);
            hs4[tid] = v;
            float4 u = make_float4(0.f, 0.f, 0.f, 0.f);
            if (i >= 1) u = __ldcg((const float4*)g_h0[(i + 1) & 1][d] + tid);
            hs4[256 + tid] = u;
        }
        __syncthreads();   // B

        // ---- dot: lane-owned precol, smem broadcast operand ----
        const bool myact = l_w ? act1 : act0;
        if (myact) {
            ull a0 = 0ull, a1 = 0ull;
            if (l_w == 0) {
#pragma unroll
                for (int kk = 0; kk < 64; kk++) {
                    const ulonglong2 hv = *(const ulonglong2*)&hs4[256 + q * 64 + kk];
                    const ull w2 = pack2(w[kk]);
                    fma2(a0, hv.x, w2);
                    fma2(a1, hv.y, w2);
                }
            } else {
#pragma unroll
                for (int kk = 0; kk < 128; kk++) {
                    const ulonglong2 hv = *(const ulonglong2*)&hs4[q * 128 + kk];
                    const ull w2 = pack2(w[kk]);
                    fma2(a0, hv.x, w2);
                    fma2(a1, hv.y, w2);
                }
            }
            ulonglong2 st2; st2.x = a0; st2.y = a1;
            *(ulonglong2*)&red[((l_w * 4 + q) * 32 + lane) * 4] = st2;
        }
        __syncthreads();   // C

        // ---- gates: sum 4 k-quarter partials, activate, write h ----
        const bool gact = gl ? act1 : act0;
        if (is_gate && gact) {
            float sh = 0.f, st = 0.f;
#pragma unroll
            for (int qq = 0; qq < 4; qq++) {
                sh += red[((gl * 4 + qq) * 32 + gj) * 4 + gr];
                st += red[((gl * 4 + qq) * 32 + gj + 16) * 4 + gr];
            }
            const int t = gl ? (i - 1) : i;
            const float ph = sh + (gl ? gbh : xh);
            const float pt = st + (gl ? gbt : xt);
            const float tg = 1.f / (1.f + __expf(-pt));
            const float cg = 1.f / (1.f + __expf(-tg));   // bug-faithful
            const float sv = tanhf(ph) * tg + hcur * cg;
            const float hnew = (t < glen) ? sv : hcur;
            hcur = hnew;
            if (gl == 0) __stcg(&g_h0[i & 1][d][c0 * 4 + g], hnew);
            else         __stcg(&g_h1[(i - 1) & 1][d][c0 * 4 + g], hnew);
        }
        __syncthreads();   // D

        // ---- publish (release orders prior stores via barrier chain) ----
        if (tid == 0) {
            asm volatile("st.release.gpu.global.u32 [%0], %1;"
                         :: "l"(&g_flag[bid * 8]), "r"(fbase + (unsigned)(i + 1))
                         : "memory");
        }

        // ---- out1 write off the critical path ----
        if (is_gate && gl == 1 && gact) {
            out1[((size_t)(i - 1) * BATCH + 4 * d + gr) * HID + c0 + gj] = hcur;
        }
    }

    // ---- epilogue: hn + frozen-tail fill ----
    if (is_gate) {
        if (gl == 0) hn[(4 * d + gr) * HID + c0 + gj] = hcur;
        else {
            hn[BATCH * HID + (4 * d + gr) * HID + c0 + gj] = hcur;
            outs[gr * 16 + gj] = hcur;
        }
    }
    __syncthreads();
    {
        const int nfill = (T_LEN - Ld) * RPD * 4;   // in float4 units
        for (int idx = tid; idx < nfill; idx += 256) {
            const int t  = Ld + (idx >> 4);
            const int rr = (idx >> 2) & 3;
            const int jj = idx & 3;
            *(float4*)&out1[((size_t)t * BATCH + 4 * d + rr) * HID + c0 + jj * 4] =
                *(const float4*)&outs[rr * 16 + jj * 4];
        }
    }

    // ---- epoch bump: exactly one block, once per run ----
    if (bid == 0 && tid == 0) *(volatile unsigned*)&g_run = R + 1u;
}

// ---------------------------------------------------------------------------
extern "C" void kernel_launch(void* const* d_in, const int* in_sizes, int n_in,
                              void* d_out, int out_size) {
    const float* input  = (const float*)d_in[0];
    const int*   length = (const int*)d_in[1];
    const float* Wih0   = (const float*)d_in[2];
    const float* Whh0   = (const float*)d_in[3];
    const float* b0     = (const float*)d_in[4];
    const float* Wih1   = (const float*)d_in[5];
    const float* Whh1   = (const float*)d_in[6];
    const float* b1     = (const float*)d_in[7];

    float* out1 = (float*)d_out;
    float* hn   = (float*)d_out + (size_t)T_LEN * BATCH * HID;

    const int smem_bytes = (32 * 65 + 32 * 64) * 4 + 256;   // worker path is larger
    static bool attr_set = false;
    if (!attr_set) {
        cudaFuncSetAttribute(fused_all, cudaFuncAttributeMaxDynamicSharedMemorySize,
                             smem_bytes);
        attr_set = true;
    }

    fused_all<<<NTOT, 256, smem_bytes>>>(
        input, Whh0, Whh1, Wih0, Wih1, b0, b1, length, out1, hn);
}

// round 11
// speedup vs baseline: 1.7116x; 1.0181x over previous
#include <cuda_runtime.h>
#include <cstdint>

// Problem constants
#define T_LEN 2048
#define BATCH 32
#define HID   256
#define G3    768
#define NSCAN 128          // 8 domains x 16 blocks
#define NDOM  8
#define BPD   16
#define RPD   4            // batch rows per domain
#define NTOT  148
#define NWORK (NTOT - NSCAN)   // 20 gemm workers
#define NTILE 8192

typedef unsigned long long ull;

// ---------------------------------------------------------------------------
// Device scratch
// ---------------------------------------------------------------------------
__device__ float g_X[(size_t)T_LEN * BATCH * 512];   // [m=t*32+b][c 512]
__device__ float g_h0[4][NDOM][HID * RPD];           // 4-deep ring, [k*4+r]
__device__ float g_h1[2][NDOM][HID * RPD];           // 2-deep ring
__device__ unsigned g_flag[256 * 8];                 // [0..127]=A, [128..255]=B
__device__ unsigned g_tcnt[T_LEN / 2];
__device__ unsigned g_run;

// ---------------------------------------------------------------------------
__device__ __forceinline__ ull pack2(float v) {
    ull r; asm("mov.b64 %0, {%1, %1};" : "=l"(r) : "f"(v)); return r;
}
__device__ __forceinline__ void fma2(ull& d, ull a, ull b) {
    asm("fma.rn.f32x2 %0, %1, %2, %0;" : "+l"(d) : "l"(a), "l"(b));
}
__device__ __forceinline__ void unpack2(ull v, float& lo, float& hi) {
    asm("mov.b64 {%0, %1}, %2;" : "=f"(lo), "=f"(hi) : "l"(v));
}
__device__ __forceinline__ void poll_ge(const unsigned* addr, unsigned target) {
    unsigned v;
    do {
        asm volatile("ld.acquire.gpu.global.u32 %0, [%1];"
                     : "=r"(v) : "l"(addr) : "memory");
    } while ((int)(v - target) < 0);
}
__device__ __forceinline__ void barA() {
    asm volatile("bar.sync 1, 128;" ::: "memory");
}
__device__ __forceinline__ void barB() {
    asm volatile("bar.sync 2, 128;" ::: "memory");
}

// ---------------------------------------------------------------------------
// GEMM worker: grid-strided 64x64x256 tiles; g_X = input@Wih0[:,:512]+b0
// ---------------------------------------------------------------------------
__device__ void gemm_worker(int wb, const float* __restrict__ A,
                            const float* __restrict__ W,
                            const float* __restrict__ bias,
                            float* smem, int Lmax)
{
    float (*As)[65] = (float(*)[65])smem;
    float (*Bs)[64] = (float(*)[64])(smem + 32 * 65);

    const int tid = threadIdx.x;
    const int tx  = tid & 15;
    const int ty  = tid >> 4;
    const int ar  = tid >> 2;
    const int ak  = (tid & 3) * 8;
    const int bk  = tid >> 3;
    const int bc  = (tid & 7) * 8;

    for (int n = wb; n < NTILE; n += NWORK) {
        const int bx = n >> 3;
        if (2 * bx >= Lmax) break;
        const int m0 = bx * 64;
        const int n0 = (n & 7) * 64;

        ull acc2[4][2];
#pragma unroll
        for (int i = 0; i < 4; i++) { acc2[i][0] = 0ull; acc2[i][1] = 0ull; }

        for (int k0 = 0; k0 < 256; k0 += 32) {
            float4 a0  = *(const float4*)&A[(size_t)(m0 + ar) * 256 + k0 + ak];
            float4 a1  = *(const float4*)&A[(size_t)(m0 + ar) * 256 + k0 + ak + 4];
            float4 b0v = *(const float4*)&W[(size_t)(k0 + bk) * G3 + n0 + bc];
            float4 b1v = *(const float4*)&W[(size_t)(k0 + bk) * G3 + n0 + bc + 4];

            As[ak + 0][ar] = a0.x; As[ak + 1][ar] = a0.y;
            As[ak + 2][ar] = a0.z; As[ak + 3][ar] = a0.w;
            As[ak + 4][ar] = a1.x; As[ak + 5][ar] = a1.y;
            As[ak + 6][ar] = a1.z; As[ak + 7][ar] = a1.w;
            *(float4*)&Bs[bk][bc]     = b0v;
            *(float4*)&Bs[bk][bc + 4] = b1v;
            __syncthreads();

#pragma unroll
            for (int kk = 0; kk < 32; kk++) {
                const ulonglong2 bq = *(const ulonglong2*)&Bs[kk][ty * 4];
#pragma unroll
                for (int ri = 0; ri < 4; ri++) {
                    const ull av = pack2(As[kk][tx * 4 + ri]);
                    fma2(acc2[ri][0], bq.x, av);
                    fma2(acc2[ri][1], bq.y, av);
                }
            }
            __syncthreads();
        }

        const float4 bv = *(const float4*)&bias[n0 + ty * 4];
#pragma unroll
        for (int ri = 0; ri < 4; ri++) {
            float4 v;
            unpack2(acc2[ri][0], v.x, v.y);
            unpack2(acc2[ri][1], v.z, v.w);
            v.x += bv.x; v.y += bv.y; v.z += bv.z; v.w += bv.w;
            *(float4*)&g_X[(size_t)(m0 + tx * 4 + ri) * 512 + n0 + ty * 4] = v;
        }

        __threadfence();
        __syncthreads();
        if (tid == 0) {
            asm volatile("red.release.gpu.global.add.u32 [%0], %1;"
                         :: "l"(&g_tcnt[bx]), "r"(1u) : "memory");
        }
    }
}

// ---------------------------------------------------------------------------
// ONE kernel, 148 blocks (1/SM):
//   blocks 0..127: scan; 8 domains x 16 blocks; block owns 16 h-cols.
//     Warps 4-7 = A-pipeline (layer 0, recurrence critical path, hi priority).
//     Warps 0-3 = B-pipeline (layer 1), independent cadence, own flag set.
//   blocks 128..147: gemm workers.
// A round a: h0(a) = f(h0(a-1), g_X row a).     Publishes A-flag = a+1.
// B round b: h1(b) = f(h1(b-1), h0(b)).         Publishes B-flag = b+1.
// A backpressure: h0 ring is 4 deep; A round a polls peers' B-flag >= a-3.
// ---------------------------------------------------------------------------
__global__ __launch_bounds__(256, 1) void fused_all(
    const float* __restrict__ input,
    const float* __restrict__ Whh0,
    const float* __restrict__ Whh1,
    const float* __restrict__ Wih0,
    const float* __restrict__ Wih1,
    const float* __restrict__ b0,
    const float* __restrict__ b1,
    const int*   __restrict__ length,
    float* __restrict__ out1,
    float* __restrict__ hn)
{
    extern __shared__ float smem[];
    const int bid = blockIdx.x;
    const int tid = threadIdx.x;

    int Lmax = 0;
#pragma unroll 8
    for (int r = 0; r < BATCH; r++) Lmax = max(Lmax, length[r]);

    if (bid >= NSCAN) {
        gemm_worker(bid - NSCAN, input, Wih0, b0, smem, Lmax);
        return;
    }

    // smem layout
    float4* hsA4 = (float4*)smem;            // [256] float4  (4KB)
    float4* hsB4 = hsA4 + 256;               // [512] float4  (8KB)
    float*  redA = (float*)(hsB4 + 512);     // [4q][32p][4r] (2KB)
    float*  redB = redA + 512;               // (2KB)
    float*  outs = redB + 512;               // [4r][16j]

    const int d   = bid >> 4;
    const int c0  = (bid & 15) * 16;

    int Ld = 0;
#pragma unroll
    for (int r = 0; r < RPD; r++) Ld = max(Ld, length[4 * d + r]);

    const unsigned R   = *(volatile unsigned*)&g_run;
    const unsigned fbA = R * (unsigned)Ld;
    const unsigned fbB = R * (unsigned)Ld;
    const unsigned tb  = R * 8u;

    const int lane = tid & 31;
    const int pc   = (lane < 16) ? (c0 + lane) : (256 + c0 + lane - 16);

    if (tid >= 128) {
        // =================== A-pipeline: layer 0 ===================
        const int atid = tid - 128;
        const int wq   = (tid >> 5) - 4;

        float wA[64];
#pragma unroll
        for (int kk = 0; kk < 64; kk++)
            wA[kk] = Whh0[(size_t)(wq * 64 + kk) * G3 + pc];

        const bool isg = (atid < 64);
        const int  gj  = atid >> 2;
        const int  gr  = atid & 3;
        const int  glen = length[4 * d + (atid & 3)];
        float hcur = 0.f;
        int rdy = 0;

        for (int a = 0; a < Ld; a++) {
            if (a > 0 && atid < 16)
                poll_ge(&g_flag[(d * 16 + atid) * 8], fbA + (unsigned)a);
            if (a >= 4 && atid >= 16 && atid < 32)
                poll_ge(&g_flag[(128 + d * 16 + atid - 16) * 8],
                        fbB + (unsigned)(a - 3));
            if (atid == 32 && (a >> 1) >= rdy) {
                poll_ge(&g_tcnt[a >> 1], tb + 8u);
                rdy = (a >> 1) + 1;
            }
            barA();

            float xh = 0.f, xt = 0.f;
            if (isg) {
                const size_t m = (size_t)a * BATCH + 4 * d + gr;
                xh = __ldg(&g_X[m * 512 + c0 + gj]);
                xt = __ldg(&g_X[m * 512 + 256 + c0 + gj]);
            }
            if (a > 0) {
                const float4* s = (const float4*)g_h0[(a - 1) & 3][d];
                hsA4[atid]       = __ldcg(s + atid);
                hsA4[128 + atid] = __ldcg(s + 128 + atid);
            } else {
                const float4 z = make_float4(0.f, 0.f, 0.f, 0.f);
                hsA4[atid] = z; hsA4[128 + atid] = z;
            }
            barA();

            ull a0 = 0ull, a1 = 0ull;
#pragma unroll
            for (int kk = 0; kk < 64; kk++) {
                const ulonglong2 hv = *(const ulonglong2*)&hsA4[wq * 64 + kk];
                const ull w2 = pack2(wA[kk]);
                fma2(a0, hv.x, w2);
                fma2(a1, hv.y, w2);
            }
            { ulonglong2 st2; st2.x = a0; st2.y = a1;
              *(ulonglong2*)&redA[(wq * 32 + lane) * 4] = st2; }
            barA();

            if (isg) {
                float sh = 0.f, st = 0.f;
#pragma unroll
                for (int q = 0; q < 4; q++) {
                    sh += redA[(q * 32 + gj) * 4 + gr];
                    st += redA[(q * 32 + gj + 16) * 4 + gr];
                }
                const float ph = sh + xh;
                const float pt = st + xt;
                const float tg = 1.f / (1.f + __expf(-pt));
                const float cg = 1.f / (1.f + __expf(-tg));  // bug-faithful
                const float sv = tanhf(ph) * tg + hcur * cg;
                const float hnew = (a < glen) ? sv : hcur;
                hcur = hnew;
                __stcg(&g_h0[a & 3][d][c0 * 4 + atid], hnew);
            }
            barA();

            if (atid == 0) {
                asm volatile("st.release.gpu.global.u32 [%0], %1;"
                             :: "l"(&g_flag[bid * 8]),
                                "r"(fbA + (unsigned)(a + 1)) : "memory");
            }
        }
        if (isg) hn[(4 * d + gr) * HID + c0 + gj] = hcur;

    } else {
        // =================== B-pipeline: layer 1 ===================
        const int wq = tid >> 5;

        float wB[128];
#pragma unroll
        for (int kk = 0; kk < 128; kk++) {
            const int k = wq * 128 + kk;
            wB[kk] = (k < 256) ? Whh1[(size_t)k * G3 + pc]
                               : Wih1[(size_t)(k - 256) * G3 + pc];
        }

        const bool isg = (tid < 64);
        const int  gj  = tid >> 2;
        const int  gr  = tid & 3;
        const int  glen = length[4 * d + (tid & 3)];
        float gbh = 0.f, gbt = 0.f;
        if (isg) { gbh = b1[c0 + gj]; gbt = b1[256 + c0 + gj]; }
        if (tid < 64) outs[tid] = 0.f;
        float hcur = 0.f;

        for (int b = 0; b < Ld; b++) {
            if (b > 0 && tid < 16)
                poll_ge(&g_flag[(128 + d * 16 + tid) * 8], fbB + (unsigned)b);
            if (tid >= 16 && tid < 32)
                poll_ge(&g_flag[(d * 16 + tid - 16) * 8], fbA + (unsigned)(b + 1));
            barB();

            if (b > 0) {
                const float4* s1 = (const float4*)g_h1[(b - 1) & 1][d];
                hsB4[tid]       = __ldcg(s1 + tid);
                hsB4[128 + tid] = __ldcg(s1 + 128 + tid);
            } else {
                const float4 z = make_float4(0.f, 0.f, 0.f, 0.f);
                hsB4[tid] = z; hsB4[128 + tid] = z;
            }
            {
                const float4* s0 = (const float4*)g_h0[b & 3][d];
                hsB4[256 + tid] = __ldcg(s0 + tid);
                hsB4[384 + tid] = __ldcg(s0 + 128 + tid);
            }
            barB();

            ull a0 = 0ull, a1 = 0ull;
#pragma unroll
            for (int kk = 0; kk < 128; kk++) {
                const ulonglong2 hv = *(const ulonglong2*)&hsB4[wq * 128 + kk];
                const ull w2 = pack2(wB[kk]);
                fma2(a0, hv.x, w2);
                fma2(a1, hv.y, w2);
            }
            { ulonglong2 st2; st2.x = a0; st2.y = a1;
              *(ulonglong2*)&redB[(wq * 32 + lane) * 4] = st2; }
            barB();

            if (isg) {
                float sh = 0.f, st = 0.f;
#pragma unroll
                for (int q = 0; q < 4; q++) {
                    sh += redB[(q * 32 + gj) * 4 + gr];
                    st += redB[(q * 32 + gj + 16) * 4 + gr];
                }
                const float ph = sh + gbh;
                const float pt = st + gbt;
                const float tg = 1.f / (1.f + __expf(-pt));
                const float cg = 1.f / (1.f + __expf(-tg));  // bug-faithful
                const float sv = tanhf(ph) * tg + hcur * cg;
                const float hnew = (b < glen) ? sv : hcur;
                hcur = hnew;
                __stcg(&g_h1[b & 1][d][c0 * 4 + tid], hnew);
            }
            barB();

            if (tid == 0) {
                asm volatile("st.release.gpu.global.u32 [%0], %1;"
                             :: "l"(&g_flag[(128 + bid) * 8]),
                                "r"(fbB + (unsigned)(b + 1)) : "memory");
            }
            // out1 write off the critical path (post-publish)
            if (isg)
                out1[((size_t)b * BATCH + 4 * d + gr) * HID + c0 + gj] = hcur;
        }

        // epilogue: hn1 + frozen-tail fill
        if (isg) {
            hn[BATCH * HID + (4 * d + gr) * HID + c0 + gj] = hcur;
            outs[gr * 16 + gj] = hcur;
        }
        barB();
        {
            const int nfill = (T_LEN - Ld) * 16;   // float4 units
            for (int idx = tid; idx < nfill; idx += 128) {
                const int t  = Ld + (idx >> 4);
                const int rr = (idx >> 2) & 3;
                const int jj = idx & 3;
                *(float4*)&out1[((size_t)t * BATCH + 4 * d + rr) * HID
                                + c0 + jj * 4] =
                    *(const float4*)&outs[rr * 16 + jj * 4];
            }
        }
        if (bid == 0 && tid == 0) *(volatile unsigned*)&g_run = R + 1u;
    }
}

// ---------------------------------------------------------------------------
extern "C" void kernel_launch(void* const* d_in, const int* in_sizes, int n_in,
                              void* d_out, int out_size) {
    const float* input  = (const float*)d_in[0];
    const int*   length = (const int*)d_in[1];
    const float* Wih0   = (const float*)d_in[2];
    const float* Whh0   = (const float*)d_in[3];
    const float* b0     = (const float*)d_in[4];
    const float* Wih1   = (const float*)d_in[5];
    const float* Whh1   = (const float*)d_in[6];
    const float* b1     = (const float*)d_in[7];

    float* out1 = (float*)d_out;
    float* hn   = (float*)d_out + (size_t)T_LEN * BATCH * HID;

    // scan: (256+512)*16 + 2KB + 2KB + 256B ; worker: 16.5KB -> take max
    const int smem_bytes = (256 * 4 + 512 * 4 + 512 + 512 + 64) * 4;
    static bool attr_set = false;
    if (!attr_set) {
        cudaFuncSetAttribute(fused_all, cudaFuncAttributeMaxDynamicSharedMemorySize,
                             smem_bytes);
        attr_set = true;
    }

    fused_all<<<NTOT, 256, smem_bytes>>>(
        input, Whh0, Whh1, Wih0, Wih1, b0, b1, length, out1, hn);
}